// round 3
// baseline (speedup 1.0000x reference)
#include <cuda_runtime.h>
#include <cuda_bf16.h>

// ---------------------------------------------------------------------------
// Net_4174708212167: 4-qubit variational circuit per 2x2 image patch + MLP.
// Inputs (metadata order): x[128,1,28,28] f32, weight[60] f32,
//   fc1_w[64,784], fc1_b[64], fc2_w[10,64], fc2_b[10]. Output: [128,10] f32.
// ---------------------------------------------------------------------------

#define NQ 4
#define NPATCH 196            // 14*14 patches per image
#define BATCH_MAX 128
#define FEAT_DIM 784          // 196 * 4

// Scratch (no cudaMalloc allowed): weight-angle cos/sin table + features.
__device__ float g_wcs[120];                       // [60][2] = cos(w/2), sin(w/2)
__device__ float g_feat[BATCH_MAX * FEAT_DIM];     // circuit features

// --- precompute cos/sin of weight half-angles (one tiny launch) ------------
__global__ void wprep_kernel(const float* __restrict__ w) {
    int i = threadIdx.x;
    if (i < 60) {
        float c, s;
        sincosf(0.5f * w[i], &s, &c);
        g_wcs[2 * i]     = c;
        g_wcs[2 * i + 1] = s;
    }
}

// --- gate primitives on a register-resident 16-amplitude statevector -------
// Qubit q corresponds to bit mask m = 8 >> q (q0 is the most significant bit).

__device__ __forceinline__ void gate_rx(float* re, float* im, int m, float cr, float si) {
    // [[c, -i s],[-i s, c]]
#pragma unroll
    for (int idx = 0; idx < 16; ++idx) {
        if (idx & m) continue;
        int k = idx | m;
        float jr = re[idx], ji = im[idx], kr = re[k], ki = im[k];
        re[idx] = cr * jr + si * ki;
        im[idx] = cr * ji - si * kr;
        re[k]   = cr * kr + si * ji;
        im[k]   = cr * ki - si * jr;
    }
}

__device__ __forceinline__ void gate_ry(float* re, float* im, int m, float cr, float sr) {
    // [[c, -s],[s, c]] (real)
#pragma unroll
    for (int idx = 0; idx < 16; ++idx) {
        if (idx & m) continue;
        int k = idx | m;
        float jr = re[idx], ji = im[idx], kr = re[k], ki = im[k];
        re[idx] = cr * jr - sr * kr;
        im[idx] = cr * ji - sr * ki;
        re[k]   = sr * jr + cr * kr;
        im[k]   = sr * ji + cr * ki;
    }
}

__device__ __forceinline__ void gate_rz(float* re, float* im, int m, float cr, float si) {
    // diag(e^{-i t/2}, e^{+i t/2})
#pragma unroll
    for (int idx = 0; idx < 16; ++idx) {
        if (idx & m) continue;
        int k = idx | m;
        float jr = re[idx], ji = im[idx], kr = re[k], ki = im[k];
        re[idx] = cr * jr + si * ji;
        im[idx] = cr * ji - si * jr;
        re[k]   = cr * kr - si * ki;
        im[k]   = cr * ki + si * kr;
    }
}

__device__ __forceinline__ void gate_cnot(float* re, float* im, int mc, int mt) {
#pragma unroll
    for (int idx = 0; idx < 16; ++idx) {
        if ((idx & mc) && !(idx & mt)) {
            int k = idx ^ mt;
            float tr = re[idx]; re[idx] = re[k]; re[k] = tr;
            float ti = im[idx]; im[idx] = im[k]; im[k] = ti;
        }
    }
}

// --- circuit kernel: one thread per patch ----------------------------------
__global__ void circuit_kernel(const float* __restrict__ x, int B) {
    int l = blockIdx.x * blockDim.x + threadIdx.x;
    if (l >= B * NPATCH) return;
    int b = l / NPATCH;
    int p = l - b * NPATCH;
    int pi = p / 14;
    int pj = p - pi * 14;

    const float* img = x + b * 784;
    // patch angles (in units of pi: t/2 = pi * x)
    float a0 = img[(2 * pi) * 28 + 2 * pj];
    float a1 = img[(2 * pi) * 28 + 2 * pj + 1];
    float a2 = img[(2 * pi + 1) * 28 + 2 * pj];
    float a3 = img[(2 * pi + 1) * 28 + 2 * pj + 1];

    float re[16], im[16];
#pragma unroll
    for (int i = 0; i < 16; ++i) { re[i] = 0.f; im[i] = 0.f; }
    re[0] = 1.f;

    // Rx data encoding: cos(pi*x), sin(pi*x)
    float c, s;
    sincospif(a0, &s, &c); gate_rx(re, im, 8, c, s);
    sincospif(a1, &s, &c); gate_rx(re, im, 4, c, s);
    sincospif(a2, &s, &c); gate_rx(re, im, 2, c, s);
    sincospif(a3, &s, &c); gate_rx(re, im, 1, c, s);

    for (int layer = 0; layer < 5; ++layer) {
        const float* wc = g_wcs + layer * 24;   // 12 gates * (c,s)
        float w0  = __ldg(wc + 0),  w1  = __ldg(wc + 1);
        float w2  = __ldg(wc + 2),  w3  = __ldg(wc + 3);
        float w4  = __ldg(wc + 4),  w5  = __ldg(wc + 5);
        float w6  = __ldg(wc + 6),  w7  = __ldg(wc + 7);
        gate_ry(re, im, 8, w0, w1);
        gate_ry(re, im, 4, w2, w3);
        gate_ry(re, im, 2, w4, w5);
        gate_ry(re, im, 1, w6, w7);
        float z0 = __ldg(wc + 8),  z1 = __ldg(wc + 9);
        float z2 = __ldg(wc + 10), z3 = __ldg(wc + 11);
        float z4 = __ldg(wc + 12), z5 = __ldg(wc + 13);
        float z6 = __ldg(wc + 14), z7 = __ldg(wc + 15);
        gate_rz(re, im, 8, z0, z1);
        gate_rz(re, im, 4, z2, z3);
        gate_rz(re, im, 2, z4, z5);
        gate_rz(re, im, 1, z6, z7);
        float y0 = __ldg(wc + 16), y1 = __ldg(wc + 17);
        float y2 = __ldg(wc + 18), y3 = __ldg(wc + 19);
        float y4 = __ldg(wc + 20), y5 = __ldg(wc + 21);
        float y6 = __ldg(wc + 22), y7 = __ldg(wc + 23);
        gate_ry(re, im, 8, y0, y1);
        gate_ry(re, im, 4, y2, y3);
        gate_ry(re, im, 2, y4, y5);
        gate_ry(re, im, 1, y6, y7);
        if (layer < 4) {
            gate_cnot(re, im, 8, 4);   // CNOT(0,1)
            gate_cnot(re, im, 4, 2);   // CNOT(1,2)
            gate_cnot(re, im, 2, 1);   // CNOT(2,3)
            gate_cnot(re, im, 1, 8);   // CNOT(3,0)
        }
    }

    // <Z_q> expectations
    float e0 = 0.f, e1 = 0.f, e2 = 0.f, e3 = 0.f;
#pragma unroll
    for (int idx = 0; idx < 16; ++idx) {
        float pr = re[idx] * re[idx] + im[idx] * im[idx];
        e0 += (idx & 8) ? -pr : pr;
        e1 += (idx & 4) ? -pr : pr;
        e2 += (idx & 2) ? -pr : pr;
        e3 += (idx & 1) ? -pr : pr;
    }

    float* f = g_feat + b * FEAT_DIM + p * 4;
    f[0] = e0; f[1] = e1; f[2] = e2; f[3] = e3;
}

// --- fused FC1 + ReLU + FC2: one block per batch row -----------------------
__global__ void fc_kernel(const float* __restrict__ w1, const float* __restrict__ b1,
                          const float* __restrict__ w2, const float* __restrict__ b2,
                          float* __restrict__ out) {
    __shared__ float sf[FEAT_DIM];
    __shared__ float sh[64];
    int b = blockIdx.x;
    int t = threadIdx.x;

    const float* frow = g_feat + b * FEAT_DIM;
    for (int i = t; i < FEAT_DIM; i += blockDim.x) sf[i] = frow[i];
    __syncthreads();

    if (t < 64) {
        const float* w = w1 + t * FEAT_DIM;
        float acc = b1[t];
#pragma unroll 4
        for (int k = 0; k < FEAT_DIM; k += 4) {
            float4 wv = *reinterpret_cast<const float4*>(w + k);
            acc += sf[k] * wv.x + sf[k + 1] * wv.y + sf[k + 2] * wv.z + sf[k + 3] * wv.w;
        }
        sh[t] = fmaxf(acc, 0.f);
    }
    __syncthreads();

    if (t < 10) {
        const float* w = w2 + t * 64;
        float acc = b2[t];
#pragma unroll
        for (int k = 0; k < 64; ++k) acc += sh[k] * w[k];
        out[b * 10 + t] = acc;
    }
}

// ---------------------------------------------------------------------------
extern "C" void kernel_launch(void* const* d_in, const int* in_sizes, int n_in,
                              void* d_out, int out_size) {
    const float* x     = (const float*)d_in[0];
    const float* wts   = (const float*)d_in[1];
    const float* fc1_w = (const float*)d_in[2];
    const float* fc1_b = (const float*)d_in[3];
    const float* fc2_w = (const float*)d_in[4];
    const float* fc2_b = (const float*)d_in[5];
    float* out = (float*)d_out;

    int B = in_sizes[0] / 784;   // 128

    wprep_kernel<<<1, 64>>>(wts);

    int total = B * NPATCH;
    int threads = 256;
    int blocks = (total + threads - 1) / threads;
    circuit_kernel<<<blocks, threads>>>(x, B);

    fc_kernel<<<B, 64>>>(fc1_w, fc1_b, fc2_w, fc2_b, out);
}

// round 6
// speedup vs baseline: 1.7146x; 1.7146x over previous
#include <cuda_runtime.h>
#include <cuda_bf16.h>

// ---------------------------------------------------------------------------
// Net_4174708212167: 4-qubit variational circuit per 2x2 image patch + MLP.
// Fully fused: one block per image. Phases within a block:
//   (1) stage image into shared (coalesced) + build 20 composed SU(2) gate
//       matrices U = Ry(c)Rz(b)Ry(a) per (layer,qubit) in shared
//   (2) 196 threads simulate one patch each (register statevector),
//       features -> shared
//   (3) FC1 (64x784, 4-way split-K across 256 threads) + ReLU -> shared
//   (4) FC2 (10x64) -> out
// ---------------------------------------------------------------------------

#define NPATCH 196
#define FEAT_DIM 784

// --- general 1-qubit gate on register-resident 16-amp statevector ----------
// Qubit mask m = 8 >> q (q0 = most significant bit).
__device__ __forceinline__ void gate_u(float* re, float* im, int m, const float* u) {
    float u00r = u[0], u00i = u[1], u01r = u[2], u01i = u[3];
    float u10r = u[4], u10i = u[5], u11r = u[6], u11i = u[7];
#pragma unroll
    for (int idx = 0; idx < 16; ++idx) {
        if (idx & m) continue;
        int k = idx | m;
        float jr = re[idx], ji = im[idx], kr = re[k], ki = im[k];
        re[idx] = u00r * jr - u00i * ji + u01r * kr - u01i * ki;
        im[idx] = u00r * ji + u00i * jr + u01r * ki + u01i * kr;
        re[k]   = u10r * jr - u10i * ji + u11r * kr - u11i * ki;
        im[k]   = u10r * ji + u10i * jr + u11r * ki + u11i * kr;
    }
}

__device__ __forceinline__ void gate_rx(float* re, float* im, int m, float cr, float si) {
#pragma unroll
    for (int idx = 0; idx < 16; ++idx) {
        if (idx & m) continue;
        int k = idx | m;
        float jr = re[idx], ji = im[idx], kr = re[k], ki = im[k];
        re[idx] = cr * jr + si * ki;
        im[idx] = cr * ji - si * kr;
        re[k]   = cr * kr + si * ji;
        im[k]   = cr * ki - si * jr;
    }
}

__device__ __forceinline__ void gate_cnot(float* re, float* im, int mc, int mt) {
#pragma unroll
    for (int idx = 0; idx < 16; ++idx) {
        if ((idx & mc) && !(idx & mt)) {
            int k = idx ^ mt;
            float tr = re[idx]; re[idx] = re[k]; re[k] = tr;
            float ti = im[idx]; im[idx] = im[k]; im[k] = ti;
        }
    }
}

// ---------------------------------------------------------------------------
__global__ void __launch_bounds__(256, 4)
fused_kernel(const float* __restrict__ x, const float* __restrict__ wts,
             const float* __restrict__ w1, const float* __restrict__ b1,
             const float* __restrict__ w2, const float* __restrict__ b2,
             float* __restrict__ out) {
    __shared__ __align__(16) float sx[FEAT_DIM];   // image pixels
    __shared__ float su[20][8];                    // composed U per (layer,qubit)
    __shared__ __align__(16) float sf[FEAT_DIM];   // circuit features
    __shared__ float spart[256];                   // FC1 partial sums
    __shared__ float sh[64];                       // FC1 activations

    const int b = blockIdx.x;
    const int t = threadIdx.x;

    // ---- phase 1: stage image + build composed gate matrices ----
    {
        const float* img = x + b * FEAT_DIM;
        const float4* img4 = reinterpret_cast<const float4*>(img);
        float4* sx4 = reinterpret_cast<float4*>(sx);
        for (int i = t; i < FEAT_DIM / 4; i += 256) sx4[i] = img4[i];
    }
    if (t < 20) {
        int l = t >> 2, q = t & 3;
        float a = wts[l * 12 + q];
        float bb = wts[l * 12 + 4 + q];
        float c = wts[l * 12 + 8 + q];
        float sa, ca, sb, cb, sc, cc;
        sincosf(0.5f * a,  &sa, &ca);
        sincosf(0.5f * bb, &sb, &cb);
        sincosf(0.5f * c,  &sc, &cc);
        // M = Rz(b)*Ry(a): row0 *= (cb - i sb), row1 *= (cb + i sb)
        float m00r =  cb * ca, m00i = -sb * ca;
        float m01r = -cb * sa, m01i =  sb * sa;
        float m10r =  cb * sa, m10i =  sb * sa;
        float m11r =  cb * ca, m11i =  sb * ca;
        // U = Ry(c)*M
        su[t][0] = cc * m00r - sc * m10r;  su[t][1] = cc * m00i - sc * m10i;
        su[t][2] = cc * m01r - sc * m11r;  su[t][3] = cc * m01i - sc * m11i;
        su[t][4] = sc * m00r + cc * m10r;  su[t][5] = sc * m00i + cc * m10i;
        su[t][6] = sc * m01r + cc * m11r;  su[t][7] = sc * m01i + cc * m11i;
    }
    __syncthreads();

    // ---- phase 2: simulate one patch per thread (threads 0..195) ----
    if (t < NPATCH) {
        int pi = t / 14;
        int pj = t - pi * 14;
        float a0 = sx[(2 * pi) * 28 + 2 * pj];
        float a1 = sx[(2 * pi) * 28 + 2 * pj + 1];
        float a2 = sx[(2 * pi + 1) * 28 + 2 * pj];
        float a3 = sx[(2 * pi + 1) * 28 + 2 * pj + 1];

        float re[16], im[16];
#pragma unroll
        for (int i = 0; i < 16; ++i) { re[i] = 0.f; im[i] = 0.f; }
        re[0] = 1.f;

        float c, s;
        sincospif(a0, &s, &c); gate_rx(re, im, 8, c, s);
        sincospif(a1, &s, &c); gate_rx(re, im, 4, c, s);
        sincospif(a2, &s, &c); gate_rx(re, im, 2, c, s);
        sincospif(a3, &s, &c); gate_rx(re, im, 1, c, s);

#pragma unroll
        for (int layer = 0; layer < 5; ++layer) {
            gate_u(re, im, 8, su[layer * 4 + 0]);
            gate_u(re, im, 4, su[layer * 4 + 1]);
            gate_u(re, im, 2, su[layer * 4 + 2]);
            gate_u(re, im, 1, su[layer * 4 + 3]);
            if (layer < 4) {
                gate_cnot(re, im, 8, 4);
                gate_cnot(re, im, 4, 2);
                gate_cnot(re, im, 2, 1);
                gate_cnot(re, im, 1, 8);
            }
        }

        float e0 = 0.f, e1 = 0.f, e2 = 0.f, e3 = 0.f;
#pragma unroll
        for (int idx = 0; idx < 16; ++idx) {
            float pr = re[idx] * re[idx] + im[idx] * im[idx];
            e0 += (idx & 8) ? -pr : pr;
            e1 += (idx & 4) ? -pr : pr;
            e2 += (idx & 2) ? -pr : pr;
            e3 += (idx & 1) ? -pr : pr;
        }
        sf[t * 4 + 0] = e0;
        sf[t * 4 + 1] = e1;
        sf[t * 4 + 2] = e2;
        sf[t * 4 + 3] = e3;
    }
    __syncthreads();

    // ---- phase 3: FC1 (64 outputs x 784), split-K by 4 ----
    {
        int j = t & 63;          // output neuron
        int q = t >> 6;          // K-quarter (196 elements)
        const float4* w4 = reinterpret_cast<const float4*>(w1 + j * FEAT_DIM + q * NPATCH);
        const float4* f4 = reinterpret_cast<const float4*>(sf + q * NPATCH);
        float acc = 0.f;
#pragma unroll 7
        for (int k = 0; k < NPATCH / 4; ++k) {
            float4 wv = w4[k];
            float4 fv = f4[k];
            acc += fv.x * wv.x + fv.y * wv.y + fv.z * wv.z + fv.w * wv.w;
        }
        spart[t] = acc;
    }
    __syncthreads();
    if (t < 64) {
        float acc = spart[t] + spart[64 + t] + spart[128 + t] + spart[192 + t] + b1[t];
        sh[t] = fmaxf(acc, 0.f);
    }
    __syncthreads();

    // ---- phase 4: FC2 (10 outputs x 64) ----
    if (t < 10) {
        const float* w = w2 + t * 64;
        float acc = b2[t];
#pragma unroll
        for (int k = 0; k < 64; ++k) acc += sh[k] * w[k];
        out[b * 10 + t] = acc;
    }
}

// ---------------------------------------------------------------------------
extern "C" void kernel_launch(void* const* d_in, const int* in_sizes, int n_in,
                              void* d_out, int out_size) {
    const float* x     = (const float*)d_in[0];
    const float* wts   = (const float*)d_in[1];
    const float* fc1_w = (const float*)d_in[2];
    const float* fc1_b = (const float*)d_in[3];
    const float* fc2_w = (const float*)d_in[4];
    const float* fc2_b = (const float*)d_in[5];
    float* out = (float*)d_out;

    int B = in_sizes[0] / FEAT_DIM;   // 128

    fused_kernel<<<B, 256>>>(x, wts, fc1_w, fc1_b, fc2_w, fc2_b, out);
}

// round 7
// speedup vs baseline: 1.9512x; 1.1380x over previous
#include <cuda_runtime.h>
#include <cuda_bf16.h>

// ---------------------------------------------------------------------------
// Net_4174708212167: 4-qubit variational circuit per 2x2 image patch + MLP.
// Fully fused: one block per image (grid=128, 256 threads, 1 CTA/SM).
//   (1) stage image (coalesced) + build 20 composed SU(2) matrices
//       U = Ry(c)Rz(b)Ry(a) per (layer,qubit) in shared
//   (1b) prefetch first FC1 weight chunk into registers (latency hidden
//        under circuit compute)
//   (2) 196 threads simulate one patch each (register statevector)
//   (3) FC1 (64x784, 4-way split-K across 256 threads) + ReLU
//   (4) FC2 (10x64) -> out
// ---------------------------------------------------------------------------

#define NPATCH 196
#define FEAT_DIM 784
#define PRE 12               // prefetched float4s per thread for FC1

// --- general 1-qubit gate on register-resident 16-amp statevector ----------
// Qubit mask m = 8 >> q (q0 = most significant bit).
__device__ __forceinline__ void gate_u(float* re, float* im, int m, const float* u) {
    const float4* u4 = reinterpret_cast<const float4*>(u);
    float4 ua = u4[0];           // u00r u00i u01r u01i
    float4 ub = u4[1];           // u10r u10i u11r u11i
    float u00r = ua.x, u00i = ua.y, u01r = ua.z, u01i = ua.w;
    float u10r = ub.x, u10i = ub.y, u11r = ub.z, u11i = ub.w;
#pragma unroll
    for (int idx = 0; idx < 16; ++idx) {
        if (idx & m) continue;
        int k = idx | m;
        float jr = re[idx], ji = im[idx], kr = re[k], ki = im[k];
        re[idx] = u00r * jr - u00i * ji + u01r * kr - u01i * ki;
        im[idx] = u00r * ji + u00i * jr + u01r * ki + u01i * kr;
        re[k]   = u10r * jr - u10i * ji + u11r * kr - u11i * ki;
        im[k]   = u10r * ji + u10i * jr + u11r * ki + u11i * kr;
    }
}

__device__ __forceinline__ void gate_rx(float* re, float* im, int m, float cr, float si) {
#pragma unroll
    for (int idx = 0; idx < 16; ++idx) {
        if (idx & m) continue;
        int k = idx | m;
        float jr = re[idx], ji = im[idx], kr = re[k], ki = im[k];
        re[idx] = cr * jr + si * ki;
        im[idx] = cr * ji - si * kr;
        re[k]   = cr * kr + si * ji;
        im[k]   = cr * ki - si * jr;
    }
}

__device__ __forceinline__ void gate_cnot(float* re, float* im, int mc, int mt) {
#pragma unroll
    for (int idx = 0; idx < 16; ++idx) {
        if ((idx & mc) && !(idx & mt)) {
            int k = idx ^ mt;
            float tr = re[idx]; re[idx] = re[k]; re[k] = tr;
            float ti = im[idx]; im[idx] = im[k]; im[k] = ti;
        }
    }
}

// ---------------------------------------------------------------------------
__global__ void __launch_bounds__(256, 1)
fused_kernel(const float* __restrict__ x, const float* __restrict__ wts,
             const float* __restrict__ w1, const float* __restrict__ b1,
             const float* __restrict__ w2, const float* __restrict__ b2,
             float* __restrict__ out) {
    __shared__ __align__(16) float sx[FEAT_DIM];   // image pixels
    __shared__ __align__(16) float su[20][8];      // composed U per (layer,qubit)
    __shared__ __align__(16) float sf[FEAT_DIM];   // circuit features
    __shared__ float spart[256];                   // FC1 partial sums
    __shared__ float sh[64];                       // FC1 activations

    const int b = blockIdx.x;
    const int t = threadIdx.x;

    // FC1 work assignment (used in phases 1b and 3)
    const int j = t & 63;          // output neuron
    const int q = t >> 6;          // K-quarter (196 elements = 49 float4)
    const float4* w4 = reinterpret_cast<const float4*>(w1 + j * FEAT_DIM + q * NPATCH);

    // ---- phase 1: stage image + build composed gate matrices ----
    {
        const float* img = x + b * FEAT_DIM;
        const float4* img4 = reinterpret_cast<const float4*>(img);
        float4* sx4 = reinterpret_cast<float4*>(sx);
        for (int i = t; i < FEAT_DIM / 4; i += 256) sx4[i] = img4[i];
    }
    if (t < 20) {
        int l = t >> 2, qq = t & 3;
        float a  = wts[l * 12 + qq];
        float bb = wts[l * 12 + 4 + qq];
        float c  = wts[l * 12 + 8 + qq];
        float sa, ca, sb, cb, sc, cc;
        sincosf(0.5f * a,  &sa, &ca);
        sincosf(0.5f * bb, &sb, &cb);
        sincosf(0.5f * c,  &sc, &cc);
        // M = Rz(b)*Ry(a): row0 *= (cb - i sb), row1 *= (cb + i sb)
        float m00r =  cb * ca, m00i = -sb * ca;
        float m01r = -cb * sa, m01i =  sb * sa;
        float m10r =  cb * sa, m10i =  sb * sa;
        float m11r =  cb * ca, m11i =  sb * ca;
        // U = Ry(c)*M
        su[t][0] = cc * m00r - sc * m10r;  su[t][1] = cc * m00i - sc * m10i;
        su[t][2] = cc * m01r - sc * m11r;  su[t][3] = cc * m01i - sc * m11i;
        su[t][4] = sc * m00r + cc * m10r;  su[t][5] = sc * m00i + cc * m10i;
        su[t][6] = sc * m01r + cc * m11r;  su[t][7] = sc * m01i + cc * m11i;
    }

    // ---- phase 1b: prefetch first FC1 weight chunk (regs are private;
    //      latency overlaps with the whole circuit phase) ----
    float4 wpre[PRE];
#pragma unroll
    for (int k = 0; k < PRE; ++k) wpre[k] = w4[k];

    __syncthreads();

    // ---- phase 2: simulate one patch per thread (threads 0..195) ----
    if (t < NPATCH) {
        int pi = t / 14;
        int pj = t - pi * 14;
        float a0 = sx[(2 * pi) * 28 + 2 * pj];
        float a1 = sx[(2 * pi) * 28 + 2 * pj + 1];
        float a2 = sx[(2 * pi + 1) * 28 + 2 * pj];
        float a3 = sx[(2 * pi + 1) * 28 + 2 * pj + 1];

        float re[16], im[16];
#pragma unroll
        for (int i = 0; i < 16; ++i) { re[i] = 0.f; im[i] = 0.f; }
        re[0] = 1.f;

        float c, s;
        sincospif(a0, &s, &c); gate_rx(re, im, 8, c, s);
        sincospif(a1, &s, &c); gate_rx(re, im, 4, c, s);
        sincospif(a2, &s, &c); gate_rx(re, im, 2, c, s);
        sincospif(a3, &s, &c); gate_rx(re, im, 1, c, s);

#pragma unroll
        for (int layer = 0; layer < 5; ++layer) {
            gate_u(re, im, 8, su[layer * 4 + 0]);
            gate_u(re, im, 4, su[layer * 4 + 1]);
            gate_u(re, im, 2, su[layer * 4 + 2]);
            gate_u(re, im, 1, su[layer * 4 + 3]);
            if (layer < 4) {
                gate_cnot(re, im, 8, 4);
                gate_cnot(re, im, 4, 2);
                gate_cnot(re, im, 2, 1);
                gate_cnot(re, im, 1, 8);
            }
        }

        float e0 = 0.f, e1 = 0.f, e2 = 0.f, e3 = 0.f;
#pragma unroll
        for (int idx = 0; idx < 16; ++idx) {
            float pr = re[idx] * re[idx] + im[idx] * im[idx];
            e0 += (idx & 8) ? -pr : pr;
            e1 += (idx & 4) ? -pr : pr;
            e2 += (idx & 2) ? -pr : pr;
            e3 += (idx & 1) ? -pr : pr;
        }
        sf[t * 4 + 0] = e0;
        sf[t * 4 + 1] = e1;
        sf[t * 4 + 2] = e2;
        sf[t * 4 + 3] = e3;
    }
    __syncthreads();

    // ---- phase 3: FC1 (64 outputs x 784), split-K by 4 ----
    {
        const float4* f4 = reinterpret_cast<const float4*>(sf + q * NPATCH);
        float acc = 0.f;
#pragma unroll
        for (int k = 0; k < PRE; ++k) {
            float4 wv = wpre[k];
            float4 fv = f4[k];
            acc += fv.x * wv.x + fv.y * wv.y + fv.z * wv.z + fv.w * wv.w;
        }
#pragma unroll
        for (int k = PRE; k < NPATCH / 4; ++k) {
            float4 wv = w4[k];
            float4 fv = f4[k];
            acc += fv.x * wv.x + fv.y * wv.y + fv.z * wv.z + fv.w * wv.w;
        }
        spart[t] = acc;
    }
    __syncthreads();
    if (t < 64) {
        float acc = spart[t] + spart[64 + t] + spart[128 + t] + spart[192 + t] + b1[t];
        sh[t] = fmaxf(acc, 0.f);
    }
    __syncthreads();

    // ---- phase 4: FC2 (10 outputs x 64) ----
    if (t < 10) {
        const float* w = w2 + t * 64;
        float acc = b2[t];
#pragma unroll
        for (int k = 0; k < 64; ++k) acc += sh[k] * w[k];
        out[b * 10 + t] = acc;
    }
}

// ---------------------------------------------------------------------------
extern "C" void kernel_launch(void* const* d_in, const int* in_sizes, int n_in,
                              void* d_out, int out_size) {
    const float* x     = (const float*)d_in[0];
    const float* wts   = (const float*)d_in[1];
    const float* fc1_w = (const float*)d_in[2];
    const float* fc1_b = (const float*)d_in[3];
    const float* fc2_w = (const float*)d_in[4];
    const float* fc2_b = (const float*)d_in[5];
    float* out = (float*)d_out;

    int B = in_sizes[0] / FEAT_DIM;   // 128

    fused_kernel<<<B, 256>>>(x, wts, fc1_w, fc1_b, fc2_w, fc2_b, out);
}